// round 4
// baseline (speedup 1.0000x reference)
#include <cuda_runtime.h>
#include <math.h>

// Problem constants (fixed by the dataset)
#define NB        8          // batch
#define C_IN      4
#define N_ETYPE   5
#define N_NTYPE   7
#define C_OUT     32
#define TEMB_CH   512
#define FAN       55         // N_ETYPE * (C_IN + N_NTYPE)
#define NMAX      400000

// Bucket layout (32 B = 8 words per (node, etype) bucket):
//   words 0..3 : float x-sums (red.add.v4.f32)
//   words 4..7 : 8 x 16-bit edge counters, fields 0..6 used (node_type one-hot)
// Zero-initialized at load; gemv re-zeros every row it consumes, so the
// zero-invariant holds across graph replays.
__device__ float g_agg[NMAX * N_ETYPE * 8];   // 64 MB
__device__ float g_h1[NB * TEMB_CH];
__device__ float g_sw2[NB * TEMB_CH];
__device__ float g_inj[NB * C_OUT];

// ---------------------------------------------------------------------------
// temb stage 1: sinusoidal embedding + lin1 + swish -> g_h1[b][512]
// ---------------------------------------------------------------------------
__global__ void temb1_kernel(const float* __restrict__ t,
                             const float* __restrict__ W1,
                             const float* __restrict__ b1) {
    __shared__ float emb[128];
    const int b = blockIdx.x;
    const int tid = threadIdx.x;

    if (tid < 64) {
        float f = expf(-(float)tid * (logf(10000.0f) / 63.0f));
        float ang = t[b] * f;
        emb[tid]      = sinf(ang);
        emb[tid + 64] = cosf(ang);
    }
    __syncthreads();

    float s = b1[tid];
    #pragma unroll 8
    for (int i = 0; i < 128; i++) s += emb[i] * W1[i * TEMB_CH + tid];
    g_h1[b * TEMB_CH + tid] = s * (1.0f / (1.0f + expf(-s)));
}

// ---------------------------------------------------------------------------
// temb stage 2: lin2 + swish -> g_sw2[b][512]
// grid = 64 (b * 8 + col_tile), 512 threads: 64 cols x 8-way K-split.
// ---------------------------------------------------------------------------
__global__ void temb2_kernel(const float* __restrict__ W2,
                             const float* __restrict__ b2) {
    __shared__ float part[8][64];
    const int b  = blockIdx.x >> 3;
    const int bo = blockIdx.x & 7;
    const int cl = threadIdx.x & 63;
    const int ks = threadIdx.x >> 6;
    const int c  = bo * 64 + cl;

    const float* h1 = g_h1 + b * TEMB_CH + ks * 64;
    const float* w  = W2 + (size_t)(ks * 64) * TEMB_CH + c;
    float s = 0.0f;
    #pragma unroll 8
    for (int i = 0; i < 64; i++) s += h1[i] * w[(size_t)i * TEMB_CH];
    part[ks][cl] = s;
    __syncthreads();

    if (threadIdx.x < 64) {
        float v = b2[bo * 64 + threadIdx.x];
        #pragma unroll
        for (int k = 0; k < 8; k++) v += part[k][threadIdx.x];
        g_sw2[b * TEMB_CH + bo * 64 + threadIdx.x] = v * (1.0f / (1.0f + expf(-v)));
    }
}

// ---------------------------------------------------------------------------
// temb stage 3: inj = sw2 @ W_temb -> g_inj[b][32]
// grid = 8, 256 threads: 32 cols x 8-way K-split.
// ---------------------------------------------------------------------------
__global__ void temb3_kernel(const float* __restrict__ Wt) {
    __shared__ float part[8][33];
    const int b  = blockIdx.x;
    const int c  = threadIdx.x & 31;
    const int ks = threadIdx.x >> 5;

    const float* sw = g_sw2 + b * TEMB_CH + ks * 64;
    const float* w  = Wt + (ks * 64) * C_OUT + c;
    float s = 0.0f;
    #pragma unroll 8
    for (int i = 0; i < 64; i++) s += sw[i] * w[i * C_OUT];
    part[ks][c] = s;
    __syncthreads();

    if (threadIdx.x < 32) {
        float v = 0.0f;
        #pragma unroll
        for (int k = 0; k < 8; k++) v += part[k][threadIdx.x];
        g_inj[b * C_OUT + threadIdx.x] = v;
    }
}

// ---------------------------------------------------------------------------
// Edge scatter, 2 edges per thread (int2 index loads).
//   bucket = row*5 + etype  (32 B)
//   bucket.x[0:4]    += x[col]            (one red.v4.f32)
//   bucket.cnt16[nt] += 1                 (one u32 red, 16-bit field)
// ---------------------------------------------------------------------------
__global__ void scatter_kernel(const int* __restrict__ ei,
                               const int* __restrict__ etype,
                               const int* __restrict__ ntype,
                               const float* __restrict__ x,
                               int E) {
    int e2 = (blockIdx.x * blockDim.x + threadIdx.x) * 2;
    if (e2 >= E) return;
    int2 rows = *reinterpret_cast<const int2*>(ei + e2);
    int2 cols = *reinterpret_cast<const int2*>(ei + E + e2);
    int2 ets  = *reinterpret_cast<const int2*>(etype + e2);

    int nt0 = __ldg(ntype + cols.x);
    int nt1 = __ldg(ntype + cols.y);
    float4 xv0 = *reinterpret_cast<const float4*>(x + (size_t)cols.x * C_IN);
    float4 xv1 = *reinterpret_cast<const float4*>(x + (size_t)cols.y * C_IN);

    float* b0 = g_agg + ((size_t)rows.x * N_ETYPE + ets.x) * 8;
    float* b1 = g_agg + ((size_t)rows.y * N_ETYPE + ets.y) * 8;

    asm volatile("red.global.add.v4.f32 [%0], {%1,%2,%3,%4};"
                 :: "l"(b0), "f"(xv0.x), "f"(xv0.y), "f"(xv0.z), "f"(xv0.w)
                 : "memory");
    asm volatile("red.global.add.v4.f32 [%0], {%1,%2,%3,%4};"
                 :: "l"(b1), "f"(xv1.x), "f"(xv1.y), "f"(xv1.z), "f"(xv1.w)
                 : "memory");
    atomicAdd(reinterpret_cast<unsigned*>(b0) + 4 + (nt0 >> 1), 1u << ((nt0 & 1) * 16));
    atomicAdd(reinterpret_cast<unsigned*>(b1) + 4 + (nt1 >> 1), 1u << ((nt1 & 1) * 16));
}

// ---------------------------------------------------------------------------
// Per-node GEMV (packed f32x2 FMA, LDS.128 weight loads) + injection + rezero.
// ---------------------------------------------------------------------------
__global__ void gemv_kernel(const float* __restrict__ Wc,
                            const int* __restrict__ batch_id,
                            float* __restrict__ out,
                            int N) {
    __shared__ float Ws[FAN * C_OUT];          // pre-scaled by 0.2
    __shared__ float injs[NB * 33];            // stride 33 avoids bank conflicts
    const int tid = threadIdx.x;
    for (int i = tid; i < FAN * C_OUT; i += blockDim.x) Ws[i] = Wc[i] * 0.2f;
    if (tid < NB * C_OUT) {
        int b = tid >> 5, c = tid & 31;
        injs[b * 33 + c] = g_inj[tid];
    }
    __syncthreads();

    int n = blockIdx.x * blockDim.x + tid;
    if (n >= N) return;

    unsigned long long acc2[C_OUT / 2];
    #pragma unroll
    for (int k = 0; k < C_OUT / 2; k++) acc2[k] = 0ULL;

    float* aggp = g_agg + (size_t)n * (N_ETYPE * 8);

    #pragma unroll
    for (int et = 0; et < N_ETYPE; et++) {
        float4 v0 = *reinterpret_cast<float4*>(aggp + et * 8);
        uint4  cw = *reinterpret_cast<uint4*>(aggp + et * 8 + 4);
        float a[11];
        a[0] = v0.x; a[1] = v0.y; a[2] = v0.z; a[3] = v0.w;
        a[4]  = (float)(cw.x & 0xFFFFu);
        a[5]  = (float)(cw.x >> 16);
        a[6]  = (float)(cw.y & 0xFFFFu);
        a[7]  = (float)(cw.y >> 16);
        a[8]  = (float)(cw.z & 0xFFFFu);
        a[9]  = (float)(cw.z >> 16);
        a[10] = (float)(cw.w & 0xFFFFu);
        #pragma unroll
        for (int j = 0; j < 11; j++) {
            unsigned long long av2;
            asm("mov.b64 %0, {%1, %1};" : "=l"(av2) : "f"(a[j]));
            const float4* Wv = reinterpret_cast<const float4*>(&Ws[(et * 11 + j) * C_OUT]);
            #pragma unroll
            for (int k4 = 0; k4 < C_OUT / 4; k4++) {
                float4 wq = Wv[k4];                 // one LDS.128 (broadcast)
                unsigned long long w01, w23;
                asm("mov.b64 %0, {%1, %2};" : "=l"(w01) : "f"(wq.x), "f"(wq.y));
                asm("mov.b64 %0, {%1, %2};" : "=l"(w23) : "f"(wq.z), "f"(wq.w));
                asm("fma.rn.f32x2 %0, %1, %2, %0;"
                    : "+l"(acc2[2 * k4 + 0]) : "l"(av2), "l"(w01));
                asm("fma.rn.f32x2 %0, %1, %2, %0;"
                    : "+l"(acc2[2 * k4 + 1]) : "l"(av2), "l"(w23));
            }
        }
    }

    int b = batch_id[n];
    const float* iv = &injs[b * 33];
    float* op = out + (size_t)n * C_OUT;
    #pragma unroll
    for (int k = 0; k < C_OUT / 2; k += 2) {
        float l0, h0, l1, h1;
        asm("mov.b64 {%0, %1}, %2;" : "=f"(l0), "=f"(h0) : "l"(acc2[k]));
        asm("mov.b64 {%0, %1}, %2;" : "=f"(l1), "=f"(h1) : "l"(acc2[k + 1]));
        float4 o;
        o.x = l0 + iv[2 * k + 0];
        o.y = h0 + iv[2 * k + 1];
        o.z = l1 + iv[2 * k + 2];
        o.w = h1 + iv[2 * k + 3];
        *reinterpret_cast<float4*>(op + 2 * k) = o;
    }

    // Re-zero this node's agg buckets (40 floats) for the next replay.
    float4 z = make_float4(0.f, 0.f, 0.f, 0.f);
    #pragma unroll
    for (int i = 0; i < N_ETYPE * 2; i++)
        reinterpret_cast<float4*>(aggp)[i] = z;
}

// ---------------------------------------------------------------------------
// Inputs (metadata order):
//  0 x [N,4] f32        1 t [8] f32          2 edge_index [2,E] i32
//  3 edge_type [E] i32  4 node_type [N] i32  5 batch_id [N] i32
//  6 W_conv [55,32] f32 7 W1 [128,512]       8 b1 [512]
//  9 W2 [512,512]      10 b2 [512]          11 W_temb [512,32]
// Output: [N,32] f32
// ---------------------------------------------------------------------------
extern "C" void kernel_launch(void* const* d_in, const int* in_sizes, int n_in,
                              void* d_out, int out_size) {
    const float* x        = (const float*)d_in[0];
    const float* t        = (const float*)d_in[1];
    const int*   ei       = (const int*)d_in[2];
    const int*   etype    = (const int*)d_in[3];
    const int*   ntype    = (const int*)d_in[4];
    const int*   batch_id = (const int*)d_in[5];
    const float* W_conv   = (const float*)d_in[6];
    const float* W1       = (const float*)d_in[7];
    const float* b1       = (const float*)d_in[8];
    const float* W2       = (const float*)d_in[9];
    const float* b2       = (const float*)d_in[10];
    const float* W_temb   = (const float*)d_in[11];
    float* out = (float*)d_out;

    const int E = in_sizes[3];
    const int N = in_sizes[4];

    // temb chain first (positions 0-2); scatter at position 3 = profiled slot.
    temb1_kernel<<<NB, TEMB_CH>>>(t, W1, b1);
    temb2_kernel<<<NB * 8, 512>>>(W2, b2);
    temb3_kernel<<<NB, 256>>>(W_temb);
    scatter_kernel<<<(E / 2 + 255) / 256, 256>>>(ei, etype, ntype, x, E);
    gemv_kernel<<<(N + 255) / 256, 256>>>(W_conv, batch_id, out, N);
}

// round 5
// speedup vs baseline: 1.1525x; 1.1525x over previous
#include <cuda_runtime.h>
#include <math.h>

// Problem constants (fixed by the dataset)
#define NB        8          // batch
#define C_IN      4
#define N_ETYPE   5
#define N_NTYPE   7
#define C_OUT     32
#define TEMB_CH   512
#define FAN       55         // N_ETYPE * (C_IN + N_NTYPE)
#define NMAX      400000

// Scatter accumulators, split by payload type:
//   g_xsum[bucket][4]  : float x-sums, hit by one red.global.add.v4.f32/edge
//   g_cnt [bucket][2]  : 7 x 8-bit edge counters (node-type one-hot), hit by
//                        one u32 red/edge. Max count per field ~10 << 255.
// bucket = node * 5 + etype. Zero at load; gemv re-zeros what it consumes,
// so the zero-invariant holds across graph replays.
__device__ float    g_xsum[NMAX * N_ETYPE * 4];   // 32 MB
__device__ unsigned g_cnt [NMAX * N_ETYPE * 2];   // 16 MB
__device__ float    g_sw2 [NB * TEMB_CH];
__device__ float    g_inj [NB * C_OUT];

// ---------------------------------------------------------------------------
// temb stage A (fused lin1+lin2): grid = 64 (b*8 + col_tile), 512 threads.
// Each block redundantly computes emb[128] and h1[512] (cheap), then does an
// 8-way K-split of its 64 lin2 output columns.
// ---------------------------------------------------------------------------
__global__ void tembA_kernel(const float* __restrict__ t,
                             const float* __restrict__ W1,
                             const float* __restrict__ b1,
                             const float* __restrict__ W2,
                             const float* __restrict__ b2) {
    __shared__ float emb[128];
    __shared__ float h1s[TEMB_CH];
    __shared__ float part[8][64];
    const int b  = blockIdx.x >> 3;
    const int bo = blockIdx.x & 7;
    const int tid = threadIdx.x;

    if (tid < 64) {
        float f = expf(-(float)tid * (logf(10000.0f) / 63.0f));
        float ang = t[b] * f;
        emb[tid]      = sinf(ang);
        emb[tid + 64] = cosf(ang);
    }
    __syncthreads();

    {   // h1[tid] = swish(emb . W1[:, tid] + b1[tid])
        float s = b1[tid];
        #pragma unroll 8
        for (int i = 0; i < 128; i++) s += emb[i] * W1[i * TEMB_CH + tid];
        h1s[tid] = s * (1.0f / (1.0f + expf(-s)));
    }
    __syncthreads();

    const int cl = tid & 63;
    const int ks = tid >> 6;
    const int c  = bo * 64 + cl;
    {
        const float* h1 = h1s + ks * 64;
        const float* w  = W2 + (size_t)(ks * 64) * TEMB_CH + c;
        float s = 0.0f;
        #pragma unroll 8
        for (int i = 0; i < 64; i++) s += h1[i] * w[(size_t)i * TEMB_CH];
        part[ks][cl] = s;
    }
    __syncthreads();

    if (tid < 64) {
        float v = b2[bo * 64 + tid];
        #pragma unroll
        for (int k = 0; k < 8; k++) v += part[k][tid];
        g_sw2[b * TEMB_CH + bo * 64 + tid] = v * (1.0f / (1.0f + expf(-v)));
    }
}

// ---------------------------------------------------------------------------
// temb stage 3: inj = sw2 @ W_temb -> g_inj[b][32]. grid = 8, 256 threads.
// ---------------------------------------------------------------------------
__global__ void temb3_kernel(const float* __restrict__ Wt) {
    __shared__ float part[8][33];
    const int b  = blockIdx.x;
    const int c  = threadIdx.x & 31;
    const int ks = threadIdx.x >> 5;

    const float* sw = g_sw2 + b * TEMB_CH + ks * 64;
    const float* w  = Wt + (ks * 64) * C_OUT + c;
    float s = 0.0f;
    #pragma unroll 8
    for (int i = 0; i < 64; i++) s += sw[i] * w[i * C_OUT];
    part[ks][c] = s;
    __syncthreads();

    if (threadIdx.x < 32) {
        float v = 0.0f;
        #pragma unroll
        for (int k = 0; k < 8; k++) v += part[k][threadIdx.x];
        g_inj[b * C_OUT + threadIdx.x] = v;
    }
}

// ---------------------------------------------------------------------------
// Edge scatter, 2 edges per thread.
//   bucket = row*5 + etype
//   g_xsum[bucket]          += x[col]       (red.v4.f32)
//   g_cnt[bucket].byte[nt]  += 1            (u32 red, 8-bit field)
// ---------------------------------------------------------------------------
__global__ void scatter_kernel(const int* __restrict__ ei,
                               const int* __restrict__ etype,
                               const int* __restrict__ ntype,
                               const float* __restrict__ x,
                               int E) {
    int e2 = (blockIdx.x * blockDim.x + threadIdx.x) * 2;
    if (e2 >= E) return;
    int2 rows = *reinterpret_cast<const int2*>(ei + e2);
    int2 cols = *reinterpret_cast<const int2*>(ei + E + e2);
    int2 ets  = *reinterpret_cast<const int2*>(etype + e2);

    int nt0 = __ldg(ntype + cols.x);
    int nt1 = __ldg(ntype + cols.y);
    float4 xv0 = *reinterpret_cast<const float4*>(x + (size_t)cols.x * C_IN);
    float4 xv1 = *reinterpret_cast<const float4*>(x + (size_t)cols.y * C_IN);

    size_t bk0 = (size_t)rows.x * N_ETYPE + ets.x;
    size_t bk1 = (size_t)rows.y * N_ETYPE + ets.y;

    asm volatile("red.global.add.v4.f32 [%0], {%1,%2,%3,%4};"
                 :: "l"(g_xsum + bk0 * 4), "f"(xv0.x), "f"(xv0.y), "f"(xv0.z), "f"(xv0.w)
                 : "memory");
    asm volatile("red.global.add.v4.f32 [%0], {%1,%2,%3,%4};"
                 :: "l"(g_xsum + bk1 * 4), "f"(xv1.x), "f"(xv1.y), "f"(xv1.z), "f"(xv1.w)
                 : "memory");
    atomicAdd(g_cnt + bk0 * 2 + (nt0 >> 2), 1u << ((nt0 & 3) * 8));
    atomicAdd(g_cnt + bk1 * 2 + (nt1 >> 2), 1u << ((nt1 & 3) * 8));
}

// ---------------------------------------------------------------------------
// Per-node GEMV (packed f32x2 FMA, LDS.128 weight loads) + injection + rezero.
// ---------------------------------------------------------------------------
__global__ void gemv_kernel(const float* __restrict__ Wc,
                            const int* __restrict__ batch_id,
                            float* __restrict__ out,
                            int N) {
    __shared__ float Ws[FAN * C_OUT];          // pre-scaled by 0.2
    __shared__ float injs[NB * 33];            // stride 33 avoids bank conflicts
    const int tid = threadIdx.x;
    for (int i = tid; i < FAN * C_OUT; i += blockDim.x) Ws[i] = Wc[i] * 0.2f;
    if (tid < NB * C_OUT) {
        int b = tid >> 5, c = tid & 31;
        injs[b * 33 + c] = g_inj[tid];
    }
    __syncthreads();

    int n = blockIdx.x * blockDim.x + tid;
    if (n >= N) return;

    unsigned long long acc2[C_OUT / 2];
    #pragma unroll
    for (int k = 0; k < C_OUT / 2; k++) acc2[k] = 0ULL;

    float*    xp = g_xsum + (size_t)n * (N_ETYPE * 4);
    unsigned* cp = g_cnt  + (size_t)n * (N_ETYPE * 2);

    #pragma unroll
    for (int et = 0; et < N_ETYPE; et++) {
        float4 v0 = *reinterpret_cast<float4*>(xp + et * 4);
        uint2  cw = *reinterpret_cast<uint2*>(cp + et * 2);
        float a[11];
        a[0] = v0.x; a[1] = v0.y; a[2] = v0.z; a[3] = v0.w;
        a[4]  = (float)( cw.x        & 0xFFu);
        a[5]  = (float)((cw.x >>  8) & 0xFFu);
        a[6]  = (float)((cw.x >> 16) & 0xFFu);
        a[7]  = (float)( cw.x >> 24);
        a[8]  = (float)( cw.y        & 0xFFu);
        a[9]  = (float)((cw.y >>  8) & 0xFFu);
        a[10] = (float)((cw.y >> 16) & 0xFFu);
        #pragma unroll
        for (int j = 0; j < 11; j++) {
            unsigned long long av2;
            asm("mov.b64 %0, {%1, %1};" : "=l"(av2) : "f"(a[j]));
            const float4* Wv = reinterpret_cast<const float4*>(&Ws[(et * 11 + j) * C_OUT]);
            #pragma unroll
            for (int k4 = 0; k4 < C_OUT / 4; k4++) {
                float4 wq = Wv[k4];                 // one LDS.128 (broadcast)
                unsigned long long w01, w23;
                asm("mov.b64 %0, {%1, %2};" : "=l"(w01) : "f"(wq.x), "f"(wq.y));
                asm("mov.b64 %0, {%1, %2};" : "=l"(w23) : "f"(wq.z), "f"(wq.w));
                asm("fma.rn.f32x2 %0, %1, %2, %0;"
                    : "+l"(acc2[2 * k4 + 0]) : "l"(av2), "l"(w01));
                asm("fma.rn.f32x2 %0, %1, %2, %0;"
                    : "+l"(acc2[2 * k4 + 1]) : "l"(av2), "l"(w23));
            }
        }
    }

    int b = batch_id[n];
    const float* iv = &injs[b * 33];
    float* op = out + (size_t)n * C_OUT;
    #pragma unroll
    for (int k = 0; k < C_OUT / 2; k += 2) {
        float l0, h0, l1, h1;
        asm("mov.b64 {%0, %1}, %2;" : "=f"(l0), "=f"(h0) : "l"(acc2[k]));
        asm("mov.b64 {%0, %1}, %2;" : "=f"(l1), "=f"(h1) : "l"(acc2[k + 1]));
        float4 o;
        o.x = l0 + iv[2 * k + 0];
        o.y = h0 + iv[2 * k + 1];
        o.z = l1 + iv[2 * k + 2];
        o.w = h1 + iv[2 * k + 3];
        *reinterpret_cast<float4*>(op + 2 * k) = o;
    }

    // Re-zero this node's accumulators for the next replay.
    float4 z4 = make_float4(0.f, 0.f, 0.f, 0.f);
    #pragma unroll
    for (int et = 0; et < N_ETYPE; et++)
        *reinterpret_cast<float4*>(xp + et * 4) = z4;
    uint2 z2 = make_uint2(0u, 0u);
    #pragma unroll
    for (int et = 0; et < N_ETYPE; et++)
        *reinterpret_cast<uint2*>(cp + et * 2) = z2;
}

// ---------------------------------------------------------------------------
// Inputs (metadata order):
//  0 x [N,4] f32        1 t [8] f32          2 edge_index [2,E] i32
//  3 edge_type [E] i32  4 node_type [N] i32  5 batch_id [N] i32
//  6 W_conv [55,32] f32 7 W1 [128,512]       8 b1 [512]
//  9 W2 [512,512]      10 b2 [512]          11 W_temb [512,32]
// Output: [N,32] f32
// ---------------------------------------------------------------------------
extern "C" void kernel_launch(void* const* d_in, const int* in_sizes, int n_in,
                              void* d_out, int out_size) {
    const float* x        = (const float*)d_in[0];
    const float* t        = (const float*)d_in[1];
    const int*   ei       = (const int*)d_in[2];
    const int*   etype    = (const int*)d_in[3];
    const int*   ntype    = (const int*)d_in[4];
    const int*   batch_id = (const int*)d_in[5];
    const float* W_conv   = (const float*)d_in[6];
    const float* W1       = (const float*)d_in[7];
    const float* b1       = (const float*)d_in[8];
    const float* W2       = (const float*)d_in[9];
    const float* b2       = (const float*)d_in[10];
    const float* W_temb   = (const float*)d_in[11];
    float* out = (float*)d_out;

    const int E = in_sizes[3];
    const int N = in_sizes[4];

    // gemv is the 4th launch -> lands in the profiled slot next round.
    tembA_kernel<<<NB * 8, 512>>>(t, W1, b1, W2, b2);
    temb3_kernel<<<NB, 256>>>(W_temb);
    scatter_kernel<<<(E / 2 + 255) / 256, 256>>>(ei, etype, ntype, x, E);
    gemv_kernel<<<(N + 255) / 256, 256>>>(W_conv, batch_id, out, N);
}

// round 6
// speedup vs baseline: 1.2172x; 1.0562x over previous
#include <cuda_runtime.h>
#include <math.h>

// Problem constants (fixed by the dataset)
#define NB        8          // batch
#define C_IN      4
#define N_ETYPE   5
#define N_NTYPE   7
#define C_OUT     32
#define TEMB_CH   512
#define FAN       55         // N_ETYPE * (C_IN + N_NTYPE)
#define NMAX      400000

// Scatter accumulators:
//   g_xsum[node][et][4] : float x-sums (red.v4.f32 target)       32 MB
//   g_cnt [node][et][2] : 7 x 8-bit counters per bucket (u32 red) 16 MB
// Zero at load; gemv re-zeros what it consumes (replay invariant).
__device__ float    g_xsum[NMAX * N_ETYPE * 4];
__device__ unsigned g_cnt [NMAX * N_ETYPE * 2];
// Packed gather row: [x0,x1,x2,x3, nt(int), pad, pad, pad] = 32 B/node.
__device__ float    g_xa  [NMAX * 8];             // 12.8 MB
__device__ float    g_sw2 [NB * TEMB_CH];
__device__ float    g_inj [NB * C_OUT];

// ---------------------------------------------------------------------------
// Prepass: pack x + node_type into one 32B row per node.
// ---------------------------------------------------------------------------
__global__ void prep_kernel(const float* __restrict__ x,
                            const int* __restrict__ ntype, int N) {
    int n = blockIdx.x * blockDim.x + threadIdx.x;
    if (n >= N) return;
    float4 xv = *reinterpret_cast<const float4*>(x + (size_t)n * C_IN);
    float* row = g_xa + (size_t)n * 8;
    *reinterpret_cast<float4*>(row) = xv;
    reinterpret_cast<int*>(row)[4] = ntype[n];
}

// ---------------------------------------------------------------------------
// temb stage A (fused lin1+lin2): grid = 64 (b*8 + col_tile), 512 threads.
// ---------------------------------------------------------------------------
__global__ void tembA_kernel(const float* __restrict__ t,
                             const float* __restrict__ W1,
                             const float* __restrict__ b1,
                             const float* __restrict__ W2,
                             const float* __restrict__ b2) {
    __shared__ float emb[128];
    __shared__ float h1s[TEMB_CH];
    __shared__ float part[8][64];
    const int b  = blockIdx.x >> 3;
    const int bo = blockIdx.x & 7;
    const int tid = threadIdx.x;

    if (tid < 64) {
        float f = expf(-(float)tid * (logf(10000.0f) / 63.0f));
        float ang = t[b] * f;
        emb[tid]      = sinf(ang);
        emb[tid + 64] = cosf(ang);
    }
    __syncthreads();

    {
        float s = b1[tid];
        #pragma unroll 8
        for (int i = 0; i < 128; i++) s += emb[i] * W1[i * TEMB_CH + tid];
        h1s[tid] = s * (1.0f / (1.0f + expf(-s)));
    }
    __syncthreads();

    const int cl = tid & 63;
    const int ks = tid >> 6;
    const int c  = bo * 64 + cl;
    {
        const float* h1 = h1s + ks * 64;
        const float* w  = W2 + (size_t)(ks * 64) * TEMB_CH + c;
        float s = 0.0f;
        #pragma unroll 8
        for (int i = 0; i < 64; i++) s += h1[i] * w[(size_t)i * TEMB_CH];
        part[ks][cl] = s;
    }
    __syncthreads();

    if (tid < 64) {
        float v = b2[bo * 64 + tid];
        #pragma unroll
        for (int k = 0; k < 8; k++) v += part[k][tid];
        g_sw2[b * TEMB_CH + bo * 64 + tid] = v * (1.0f / (1.0f + expf(-v)));
    }
}

// ---------------------------------------------------------------------------
// temb stage 3: inj = sw2 @ W_temb -> g_inj[b][32]. grid = 8, 256 threads.
// ---------------------------------------------------------------------------
__global__ void temb3_kernel(const float* __restrict__ Wt) {
    __shared__ float part[8][33];
    const int b  = blockIdx.x;
    const int c  = threadIdx.x & 31;
    const int ks = threadIdx.x >> 5;

    const float* sw = g_sw2 + b * TEMB_CH + ks * 64;
    const float* w  = Wt + (ks * 64) * C_OUT + c;
    float s = 0.0f;
    #pragma unroll 8
    for (int i = 0; i < 64; i++) s += sw[i] * w[i * C_OUT];
    part[ks][c] = s;
    __syncthreads();

    if (threadIdx.x < 32) {
        float v = 0.0f;
        #pragma unroll
        for (int k = 0; k < 8; k++) v += part[k][threadIdx.x];
        g_inj[b * C_OUT + threadIdx.x] = v;
    }
}

// ---------------------------------------------------------------------------
// Edge scatter, 2 edges per thread. Gather = one 32B row from g_xa.
//   g_xsum[row*5+et]         += x[col]   (red.v4.f32)
//   g_cnt [row*5+et].b[nt]   += 1        (u32 red, 8-bit field)
// ---------------------------------------------------------------------------
__global__ void scatter_kernel(const int* __restrict__ ei,
                               const int* __restrict__ etype,
                               int E) {
    int e2 = (blockIdx.x * blockDim.x + threadIdx.x) * 2;
    if (e2 >= E) return;
    int2 rows = *reinterpret_cast<const int2*>(ei + e2);
    int2 cols = *reinterpret_cast<const int2*>(ei + E + e2);
    int2 ets  = *reinterpret_cast<const int2*>(etype + e2);

    const float* r0 = g_xa + (size_t)cols.x * 8;
    const float* r1 = g_xa + (size_t)cols.y * 8;
    float4 xv0 = *reinterpret_cast<const float4*>(r0);
    float4 xv1 = *reinterpret_cast<const float4*>(r1);
    int nt0 = reinterpret_cast<const int*>(r0)[4];
    int nt1 = reinterpret_cast<const int*>(r1)[4];

    size_t bk0 = (size_t)rows.x * N_ETYPE + ets.x;
    size_t bk1 = (size_t)rows.y * N_ETYPE + ets.y;

    asm volatile("red.global.add.v4.f32 [%0], {%1,%2,%3,%4};"
                 :: "l"(g_xsum + bk0 * 4), "f"(xv0.x), "f"(xv0.y), "f"(xv0.z), "f"(xv0.w)
                 : "memory");
    asm volatile("red.global.add.v4.f32 [%0], {%1,%2,%3,%4};"
                 :: "l"(g_xsum + bk1 * 4), "f"(xv1.x), "f"(xv1.y), "f"(xv1.z), "f"(xv1.w)
                 : "memory");
    atomicAdd(g_cnt + bk0 * 2 + (nt0 >> 2), 1u << ((nt0 & 3) * 8));
    atomicAdd(g_cnt + bk1 * 2 + (nt1 >> 2), 1u << ((nt1 & 3) * 8));
}

// ---------------------------------------------------------------------------
// Per-node GEMV v2: each thread handles 2 nodes x 16 channels, so every
// shared-memory weight load (4x LDS.128 per j) feeds 16 FFMA2 (4:1 ratio).
// thread: gt = gid; h = gt&1 (channel half), nodes n0 = (gt>>1)*2, n0+1.
// ---------------------------------------------------------------------------
__global__ void gemv_kernel(const float* __restrict__ Wc,
                            const int* __restrict__ batch_id,
                            float* __restrict__ out,
                            int N) {
    __shared__ float Ws[FAN * C_OUT];          // pre-scaled by 0.2
    __shared__ float injs[NB * 33];
    const int tid = threadIdx.x;
    for (int i = tid; i < FAN * C_OUT; i += blockDim.x) Ws[i] = Wc[i] * 0.2f;
    if (tid < NB * C_OUT) {
        int b = tid >> 5, c = tid & 31;
        injs[b * 33 + c] = g_inj[tid];
    }
    __syncthreads();

    int gt = blockIdx.x * blockDim.x + tid;
    int h  = gt & 1;                 // channel half: [h*16, h*16+16)
    int n0 = (gt >> 1) * 2;          // this thread's node pair
    if (n0 >= N) return;

    unsigned long long acc0[8], acc1[8];
    #pragma unroll
    for (int k = 0; k < 8; k++) { acc0[k] = 0ULL; acc1[k] = 0ULL; }

    float*    xp = g_xsum + (size_t)n0 * (N_ETYPE * 4);
    unsigned* cp = g_cnt  + (size_t)n0 * (N_ETYPE * 2);

    #pragma unroll
    for (int et = 0; et < N_ETYPE; et++) {
        float4 v0 = *reinterpret_cast<float4*>(xp + et * 4);
        float4 v1 = *reinterpret_cast<float4*>(xp + N_ETYPE * 4 + et * 4);
        uint2  c0 = *reinterpret_cast<uint2*>(cp + et * 2);
        uint2  c1 = *reinterpret_cast<uint2*>(cp + N_ETYPE * 2 + et * 2);
        float a0[11], a1[11];
        a0[0] = v0.x; a0[1] = v0.y; a0[2] = v0.z; a0[3] = v0.w;
        a0[4]  = (float)( c0.x        & 0xFFu);
        a0[5]  = (float)((c0.x >>  8) & 0xFFu);
        a0[6]  = (float)((c0.x >> 16) & 0xFFu);
        a0[7]  = (float)( c0.x >> 24);
        a0[8]  = (float)( c0.y        & 0xFFu);
        a0[9]  = (float)((c0.y >>  8) & 0xFFu);
        a0[10] = (float)((c0.y >> 16) & 0xFFu);
        a1[0] = v1.x; a1[1] = v1.y; a1[2] = v1.z; a1[3] = v1.w;
        a1[4]  = (float)( c1.x        & 0xFFu);
        a1[5]  = (float)((c1.x >>  8) & 0xFFu);
        a1[6]  = (float)((c1.x >> 16) & 0xFFu);
        a1[7]  = (float)( c1.x >> 24);
        a1[8]  = (float)( c1.y        & 0xFFu);
        a1[9]  = (float)((c1.y >>  8) & 0xFFu);
        a1[10] = (float)((c1.y >> 16) & 0xFFu);

        #pragma unroll
        for (int j = 0; j < 11; j++) {
            const float4* Wv =
                reinterpret_cast<const float4*>(&Ws[(et * 11 + j) * C_OUT + h * 16]);
            unsigned long long av0, av1;
            asm("mov.b64 %0, {%1, %1};" : "=l"(av0) : "f"(a0[j]));
            asm("mov.b64 %0, {%1, %1};" : "=l"(av1) : "f"(a1[j]));
            #pragma unroll
            for (int k4 = 0; k4 < 4; k4++) {
                float4 wq = Wv[k4];                 // one LDS.128 per 2 pairs
                unsigned long long wlo, whi;
                asm("mov.b64 %0, {%1, %2};" : "=l"(wlo) : "f"(wq.x), "f"(wq.y));
                asm("mov.b64 %0, {%1, %2};" : "=l"(whi) : "f"(wq.z), "f"(wq.w));
                asm("fma.rn.f32x2 %0, %1, %2, %0;"
                    : "+l"(acc0[2 * k4 + 0]) : "l"(av0), "l"(wlo));
                asm("fma.rn.f32x2 %0, %1, %2, %0;"
                    : "+l"(acc0[2 * k4 + 1]) : "l"(av0), "l"(whi));
                asm("fma.rn.f32x2 %0, %1, %2, %0;"
                    : "+l"(acc1[2 * k4 + 0]) : "l"(av1), "l"(wlo));
                asm("fma.rn.f32x2 %0, %1, %2, %0;"
                    : "+l"(acc1[2 * k4 + 1]) : "l"(av1), "l"(whi));
            }
        }
    }

    int b0 = batch_id[n0];
    int b1 = batch_id[n0 + 1];
    const float* iv0 = &injs[b0 * 33 + h * 16];
    const float* iv1 = &injs[b1 * 33 + h * 16];
    float* op0 = out + (size_t)n0 * C_OUT + h * 16;
    float* op1 = op0 + C_OUT;
    #pragma unroll
    for (int k = 0; k < 8; k += 2) {
        float l0, h0, l1, h1;
        asm("mov.b64 {%0, %1}, %2;" : "=f"(l0), "=f"(h0) : "l"(acc0[k]));
        asm("mov.b64 {%0, %1}, %2;" : "=f"(l1), "=f"(h1) : "l"(acc0[k + 1]));
        float4 o; o.x = l0 + iv0[2*k]; o.y = h0 + iv0[2*k+1];
        o.z = l1 + iv0[2*k+2]; o.w = h1 + iv0[2*k+3];
        *reinterpret_cast<float4*>(op0 + 2 * k) = o;
        asm("mov.b64 {%0, %1}, %2;" : "=f"(l0), "=f"(h0) : "l"(acc1[k]));
        asm("mov.b64 {%0, %1}, %2;" : "=f"(l1), "=f"(h1) : "l"(acc1[k + 1]));
        float4 p; p.x = l0 + iv1[2*k]; p.y = h0 + iv1[2*k+1];
        p.z = l1 + iv1[2*k+2]; p.w = h1 + iv1[2*k+3];
        *reinterpret_cast<float4*>(op1 + 2 * k) = p;
    }

    // Re-zero: thread h==0 clears node n0, h==1 clears node n0+1.
    {
        float*    zxp = xp + h * (N_ETYPE * 4);
        unsigned* zcp = cp + h * (N_ETYPE * 2);
        float4 z4 = make_float4(0.f, 0.f, 0.f, 0.f);
        #pragma unroll
        for (int et = 0; et < N_ETYPE; et++)
            *reinterpret_cast<float4*>(zxp + et * 4) = z4;
        uint2 z2 = make_uint2(0u, 0u);
        #pragma unroll
        for (int et = 0; et < N_ETYPE; et++)
            *reinterpret_cast<uint2*>(zcp + et * 2) = z2;
    }
}

// ---------------------------------------------------------------------------
// Inputs (metadata order):
//  0 x [N,4] f32        1 t [8] f32          2 edge_index [2,E] i32
//  3 edge_type [E] i32  4 node_type [N] i32  5 batch_id [N] i32
//  6 W_conv [55,32] f32 7 W1 [128,512]       8 b1 [512]
//  9 W2 [512,512]      10 b2 [512]          11 W_temb [512,32]
// Output: [N,32] f32
// ---------------------------------------------------------------------------
extern "C" void kernel_launch(void* const* d_in, const int* in_sizes, int n_in,
                              void* d_out, int out_size) {
    const float* x        = (const float*)d_in[0];
    const float* t        = (const float*)d_in[1];
    const int*   ei       = (const int*)d_in[2];
    const int*   etype    = (const int*)d_in[3];
    const int*   ntype    = (const int*)d_in[4];
    const int*   batch_id = (const int*)d_in[5];
    const float* W_conv   = (const float*)d_in[6];
    const float* W1       = (const float*)d_in[7];
    const float* b1       = (const float*)d_in[8];
    const float* W2       = (const float*)d_in[9];
    const float* b2       = (const float*)d_in[10];
    const float* W_temb   = (const float*)d_in[11];
    float* out = (float*)d_out;

    const int E = in_sizes[3];
    const int N = in_sizes[4];

    prep_kernel<<<(N + 255) / 256, 256>>>(x, ntype, N);
    tembA_kernel<<<NB * 8, 512>>>(t, W1, b1, W2, b2);
    temb3_kernel<<<NB, 256>>>(W_temb);
    scatter_kernel<<<(E / 2 + 255) / 256, 256>>>(ei, etype, E);   // profiled slot
    gemv_kernel<<<(N + 255) / 256, 256>>>(W_conv, batch_id, out, N);
}